// round 7
// baseline (speedup 1.0000x reference)
#include <cuda_runtime.h>

// Problem constants
#define Bb   128
#define Tt   256
#define Nn   16
#define Kk   10
#define Hh   20
#define KT   (Kk*Tt)        // 2560

typedef unsigned long long u64;

__device__ float g_sq[KT];          // per-(k,t) squared diffs
__device__ unsigned int g_ctr;      // completion counter (zero-init)

// ---------------- packed f32x2 helpers ----------------
__device__ __forceinline__ u64 pk(float lo, float hi) {
    u64 r; asm("mov.b64 %0,{%1,%2};" : "=l"(r) : "f"(lo), "f"(hi)); return r;
}
__device__ __forceinline__ float2 up(u64 v) {
    float2 f; asm("mov.b64 {%0,%1},%2;" : "=f"(f.x), "=f"(f.y) : "l"(v)); return f;
}
#define FMA2(d,a,b,c) asm("fma.rn.f32x2 %0,%1,%2,%3;" : "=l"(d) : "l"(a), "l"(b), "l"(c))
#define ADD2(d,a,b)   asm("add.rn.f32x2 %0,%1,%2;"    : "=l"(d) : "l"(a), "l"(b))
#define MUL2(d,a,b)   asm("mul.rn.f32x2 %0,%1,%2;"    : "=l"(d) : "l"(a), "l"(b))

__device__ __forceinline__ u64 relu2(u64 v) {
    float2 f = up(v);
    return pk(fmaxf(f.x, 0.f), fmaxf(f.y, 0.f));
}

// ---------------------------------------------------------------------------
// Fused kernel. Block = (t-pair, k): 16 n x 128 b x 2 t.
//  1. cooperative load of x slice + per-(t,n) standardization stats
//  2. 8 n-pair packed MLPs (pack = {n0,n1}), 2 t-packs per pair (ILP 2),
//     LN1 in-register, LN2 folded into head via streamed stats
//  3. per-(k,t) penalty: t-stats over b, product over n (prod_marginals
//     underflows to exactly 0 in fp32, so d^2 = prod_joint^2)
//  4. completion-counter last-block reduction -> scalar out
// grid = (Tt/2, Kk) = (128, 10), 128 threads (thread = b).
// ---------------------------------------------------------------------------
__global__ void __launch_bounds__(128) fused_kernel(
    const float* __restrict__ x,
    const float* __restrict__ W1, const float* __restrict__ b1,
    const float* __restrict__ W2, const float* __restrict__ b2,
    const float* __restrict__ W3, const float* __restrict__ b3,
    float* __restrict__ out)
{
    __shared__ __align__(16) ulonglong2 sw2[8][Hh][10];   // [p][o][q]: {i=2q, i=2q+1} packed {n0,n1}
    __shared__ __align__(16) ulonglong2 sl1[8][Hh];       // {w1 pack, b1 pack}
    __shared__ __align__(16) ulonglong2 sl2e[8][Hh];      // {b2 pack, w3 pack}
    __shared__ __align__(16) ulonglong2 shead[8];         // {w3sum pack, b3 pack}
    __shared__ float xtile[32][132];                      // [n*2+dt][b]
    __shared__ float2 xcoef[32];                          // {ri, -mu*ri} per (n,dt)
    __shared__ __align__(16) u64 ptile[8][2][130];        // t-value packs [p][dt][b]
    __shared__ float4 tcoef[16];                          // {r0,c0,r1,c1} per (p,dt)
    __shared__ float sred[2][4];
    __shared__ unsigned int s_last;

    int tid = threadIdx.x;
    int b   = tid;
    int t0  = blockIdx.x * 2;
    int k   = blockIdx.y;

    // ---- weight load + pack ----
    {
        const float* W2k = W2 + k * Nn * Hh * Hh;
        for (int idx = tid; idx < 1600; idx += 128) {
            int p = idx / 200, rem = idx % 200, o = rem / 10, q = rem % 10;
            const float* wa = W2k + ((2 * p)     * Hh + o) * Hh;
            const float* wb = W2k + ((2 * p + 1) * Hh + o) * Hh;
            ulonglong2 v;
            v.x = pk(wa[2 * q],     wb[2 * q]);
            v.y = pk(wa[2 * q + 1], wb[2 * q + 1]);
            sw2[p][o][q] = v;
        }
        const float* W1k = W1 + k * Nn * Hh;
        const float* b1k = b1 + k * Nn * Hh;
        const float* b2k = b2 + k * Nn * Hh;
        const float* W3k = W3 + k * Nn * Hh;
        for (int idx = tid; idx < 160; idx += 128) {
            int p = idx / 20, i = idx % 20;
            ulonglong2 v;
            v.x = pk(W1k[(2 * p) * Hh + i], W1k[(2 * p + 1) * Hh + i]);
            v.y = pk(b1k[(2 * p) * Hh + i], b1k[(2 * p + 1) * Hh + i]);
            sl1[p][i] = v;
            ulonglong2 e;
            e.x = pk(b2k[(2 * p) * Hh + i], b2k[(2 * p + 1) * Hh + i]);
            e.y = pk(W3k[(2 * p) * Hh + i], W3k[(2 * p + 1) * Hh + i]);
            sl2e[p][i] = e;
        }
        if (tid < 8) {
            float sa = 0.f, sb = 0.f;
#pragma unroll
            for (int i = 0; i < Hh; i++) {
                sa += W3k[(2 * tid) * Hh + i];
                sb += W3k[(2 * tid + 1) * Hh + i];
            }
            ulonglong2 v;
            v.x = pk(sa, sb);
            v.y = pk(b3[k * Nn + 2 * tid], b3[k * Nn + 2 * tid + 1]);
            shead[tid] = v;
        }
    }

    // ---- x load: thread b loads 2 t x 16 n ----
#pragma unroll
    for (int dt = 0; dt < 2; dt++) {
#pragma unroll
        for (int nq = 0; nq < 4; nq++) {
            float4 v = *(const float4*)(x + ((size_t)(b * Tt + t0 + dt)) * Nn + nq * 4);
            xtile[(nq * 4 + 0) * 2 + dt][b] = v.x;
            xtile[(nq * 4 + 1) * 2 + dt][b] = v.y;
            xtile[(nq * 4 + 2) * 2 + dt][b] = v.z;
            xtile[(nq * 4 + 3) * 2 + dt][b] = v.w;
        }
    }
    __syncthreads();

    // ---- x stats per (n,dt) column over b (ddof=1, no eps) ----
    {
        int col = tid >> 2, sub = tid & 3;
        float S = 0.f, Q = 0.f;
#pragma unroll 8
        for (int i = 0; i < 32; i++) {
            float v = xtile[col][sub * 32 + i];
            S += v; Q = fmaf(v, v, Q);
        }
        S += __shfl_xor_sync(0xffffffffu, S, 1);
        Q += __shfl_xor_sync(0xffffffffu, Q, 1);
        S += __shfl_xor_sync(0xffffffffu, S, 2);
        Q += __shfl_xor_sync(0xffffffffu, Q, 2);
        if (sub == 0) {
            float mu = S * (1.f / 128.f);
            float ri = 1.f / sqrtf((Q - S * mu) * (1.f / 127.f));
            xcoef[col] = make_float2(ri, -mu * ri);
        }
    }
    __syncthreads();

    const u64 ZERO = 0ull;
    const u64 c005  = pk(0.05f, 0.05f);
    const u64 cn005 = pk(-0.05f, -0.05f);

    // ---- MLP loop over 8 n-pairs, 2 t-packs each ----
#pragma unroll 1
    for (int p = 0; p < 8; p++) {
        // standardized x packs: xp[dt] = {xn(n0), xn(n1)}
        u64 xp[2];
#pragma unroll
        for (int dt = 0; dt < 2; dt++) {
            float2 c0 = xcoef[(2 * p) * 2 + dt];
            float2 c1 = xcoef[(2 * p + 1) * 2 + dt];
            float x0 = xtile[(2 * p) * 2 + dt][b];
            float x1 = xtile[(2 * p + 1) * 2 + dt][b];
            xp[dt] = pk(fmaf(x0, c0.x, c0.y), fmaf(x1, c1.x, c1.y));
        }

        // layer 1 + streamed LN1 stats
        u64 h[2][Hh];
        u64 s1[2], q1[2];
        s1[0] = ZERO; s1[1] = ZERO; q1[0] = ZERO; q1[1] = ZERO;
#pragma unroll
        for (int i = 0; i < Hh; i++) {
            ulonglong2 wb = sl1[p][i];
#pragma unroll
            for (int dt = 0; dt < 2; dt++) {
                u64 t; FMA2(t, xp[dt], wb.x, wb.y);
                t = relu2(t);
                h[dt][i] = t;
                ADD2(s1[dt], s1[dt], t);
                FMA2(q1[dt], t, t, q1[dt]);
            }
        }
        // LN1 in place
#pragma unroll
        for (int dt = 0; dt < 2; dt++) {
            u64 mu, nmu, ex, var;
            MUL2(mu,  s1[dt], c005);
            MUL2(nmu, s1[dt], cn005);
            MUL2(ex,  q1[dt], c005);
            FMA2(var, mu, nmu, ex);
            float2 vf = up(var);
            float rx = rsqrtf(vf.x + 1e-5f);
            float ry = rsqrtf(vf.y + 1e-5f);
            u64 r1 = pk(rx, ry);
            u64 v1; MUL2(v1, nmu, r1);
#pragma unroll
            for (int i = 0; i < Hh; i++)
                FMA2(h[dt][i], h[dt][i], r1, v1);
        }

        // layer 2; accumulators start at b2; stream LN2 stats + W3 dot
        u64 s2[2], q2[2], d3[2];
        s2[0] = ZERO; s2[1] = ZERO; q2[0] = ZERO; q2[1] = ZERO; d3[0] = ZERO; d3[1] = ZERO;
#pragma unroll 2
        for (int o = 0; o < Hh; o++) {
            ulonglong2 bw = sl2e[p][o];     // {b2 pack, w3 pack}
            u64 a[2]; a[0] = bw.x; a[1] = bw.x;
#pragma unroll
            for (int q = 0; q < 10; q++) {
                ulonglong2 wv = sw2[p][o][q];
#pragma unroll
                for (int dt = 0; dt < 2; dt++) {
                    FMA2(a[dt], h[dt][2 * q],     wv.x, a[dt]);
                    FMA2(a[dt], h[dt][2 * q + 1], wv.y, a[dt]);
                }
            }
#pragma unroll
            for (int dt = 0; dt < 2; dt++) {
                u64 h2 = relu2(a[dt]);
                ADD2(s2[dt], s2[dt], h2);
                FMA2(q2[dt], h2, h2, q2[dt]);
                FMA2(d3[dt], h2, bw.y, d3[dt]);
            }
        }

        // LN2 fold + head; write t-value pack
        ulonglong2 hd = shead[p];
#pragma unroll
        for (int dt = 0; dt < 2; dt++) {
            u64 mu2, nmu2, ex2, var2;
            MUL2(mu2,  s2[dt], c005);
            MUL2(nmu2, s2[dt], cn005);
            MUL2(ex2,  q2[dt], c005);
            FMA2(var2, mu2, nmu2, ex2);
            float2 vf = up(var2);
            float rx = rsqrtf(vf.x + 1e-5f);
            float ry = rsqrtf(vf.y + 1e-5f);
            u64 r2 = pk(rx, ry);
            u64 tmp; FMA2(tmp, nmu2, hd.x, d3[dt]);
            u64 o2;  FMA2(o2, r2, tmp, hd.y);
            ptile[p][dt][b] = o2;
        }
    }
    __syncthreads();

    // ---- t stats per (p,dt) over b: r = 1/(std+1e-8), c = -mu*r per half ----
    {
        int c = tid >> 3, sub = tid & 7;     // c = p*2+dt
        int pp = c >> 1, dt = c & 1;
        float Sx = 0.f, Qx = 0.f, Sy = 0.f, Qy = 0.f;
#pragma unroll
        for (int i = 0; i < 16; i++) {
            float2 v = up(ptile[pp][dt][sub * 16 + i]);
            Sx += v.x; Qx = fmaf(v.x, v.x, Qx);
            Sy += v.y; Qy = fmaf(v.y, v.y, Qy);
        }
#pragma unroll
        for (int o = 4; o; o >>= 1) {
            Sx += __shfl_xor_sync(0xffffffffu, Sx, o);
            Qx += __shfl_xor_sync(0xffffffffu, Qx, o);
            Sy += __shfl_xor_sync(0xffffffffu, Sy, o);
            Qy += __shfl_xor_sync(0xffffffffu, Qy, o);
        }
        if (sub == 0) {
            float mux = Sx * (1.f / 128.f);
            float rx  = 1.f / (sqrtf((Qx - Sx * mux) * (1.f / 127.f)) + 1e-8f);
            float muy = Sy * (1.f / 128.f);
            float ry  = 1.f / (sqrtf((Qy - Sy * muy) * (1.f / 127.f)) + 1e-8f);
            tcoef[c] = make_float4(rx, -mux * rx, ry, -muy * ry);
        }
    }
    __syncthreads();

    // ---- product over n per (b,dt); block-reduce; d^2 = pj^2 ----
    {
        int wid = tid >> 5, lane = tid & 31;
#pragma unroll
        for (int dt = 0; dt < 2; dt++) {
            float prod = 1.f;
#pragma unroll
            for (int p = 0; p < 8; p++) {
                float4 tc = tcoef[p * 2 + dt];
                float2 v  = up(ptile[p][dt][b]);
                prod *= fmaf(v.x, tc.x, tc.y);
                prod *= fmaf(v.y, tc.z, tc.w);
            }
#pragma unroll
            for (int o = 16; o; o >>= 1)
                prod += __shfl_xor_sync(0xffffffffu, prod, o);
            if (lane == 0) sred[dt][wid] = prod;
        }
    }
    __syncthreads();
    if (tid < 2) {
        float pj = (sred[tid][0] + sred[tid][1] + sred[tid][2] + sred[tid][3]) * (1.f / 128.f);
        g_sq[k * Tt + t0 + tid] = pj * pj;
    }

    // ---- completion counter: last block reduces g_sq deterministically ----
    __threadfence();
    __syncthreads();
    if (tid == 0) {
        unsigned int t = atomicAdd(&g_ctr, 1u);
        s_last = (t == (unsigned int)(gridDim.x * gridDim.y - 1)) ? 1u : 0u;
    }
    __syncthreads();
    if (s_last) {
        __threadfence();
        float acc = 0.f;
        for (int i = tid; i < KT; i += 128) acc += g_sq[i];
#pragma unroll
        for (int o = 16; o; o >>= 1) acc += __shfl_xor_sync(0xffffffffu, acc, o);
        if ((tid & 31) == 0) sred[0][tid >> 5] = acc;
        __syncthreads();
        if (tid == 0) {
            out[0] = (sred[0][0] + sred[0][1] + sred[0][2] + sred[0][3]) * (1.f / (float)KT);
            g_ctr = 0u;   // reset for next graph replay
        }
    }
}

// ---------------------------------------------------------------------------
extern "C" void kernel_launch(void* const* d_in, const int* in_sizes, int n_in,
                              void* d_out, int out_size) {
    const float* x  = (const float*)d_in[0];
    const float* W1 = (const float*)d_in[1];
    const float* b1 = (const float*)d_in[2];
    const float* W2 = (const float*)d_in[3];
    const float* b2 = (const float*)d_in[4];
    const float* W3 = (const float*)d_in[5];
    const float* b3 = (const float*)d_in[6];

    dim3 grid(Tt / 2, Kk);
    fused_kernel<<<grid, 128>>>(x, W1, b1, W2, b2, W3, b3, (float*)d_out);
}

// round 8
// speedup vs baseline: 1.0291x; 1.0291x over previous
#include <cuda_runtime.h>

// Problem constants
#define Bb   128
#define Tt   256
#define Nn   16
#define Kk   10
#define Hh   20
#define KT   (Kk*Tt)        // 2560

typedef unsigned long long u64;

__device__ float g_sq[KT];          // per-(k,t) squared diffs
__device__ unsigned int g_ctr;      // completion counter (zero-init)

// ---------------- packed f32x2 helpers ----------------
__device__ __forceinline__ u64 pk(float lo, float hi) {
    u64 r; asm("mov.b64 %0,{%1,%2};" : "=l"(r) : "f"(lo), "f"(hi)); return r;
}
__device__ __forceinline__ float2 up(u64 v) {
    float2 f; asm("mov.b64 {%0,%1},%2;" : "=f"(f.x), "=f"(f.y) : "l"(v)); return f;
}
#define FMA2(d,a,b,c) asm("fma.rn.f32x2 %0,%1,%2,%3;" : "=l"(d) : "l"(a), "l"(b), "l"(c))
#define ADD2(d,a,b)   asm("add.rn.f32x2 %0,%1,%2;"    : "=l"(d) : "l"(a), "l"(b))
#define MUL2(d,a,b)   asm("mul.rn.f32x2 %0,%1,%2;"    : "=l"(d) : "l"(a), "l"(b))

__device__ __forceinline__ u64 relu2(u64 v) {
    float2 f = up(v);
    return pk(fmaxf(f.x, 0.f), fmaxf(f.y, 0.f));
}

// dynamic smem layout (16B units where needed)
#define SW2_OFF   0                         // ulonglong2[8][20][10]  25600 B
#define SL1_OFF   1600                      // ulonglong2[8][20]       2560 B
#define SL2E_OFF  (1600 + 160)              // ulonglong2[8][20]       2560 B
#define SHEAD_OFF (1600 + 320)              // ulonglong2[8]            128 B
#define PT_BYTES  (8 * 4 * 130 * 8)         // u64[8][4][130]         33280 B
#define XT_BYTES  (64 * 132 * 4)            // float[64][132]         33792 B
#define DSMEM_TOTAL (30848 + PT_BYTES + XT_BYTES + 512 + 512)   // 98944 B

// ---------------------------------------------------------------------------
// Fused kernel, t-quad. Block = (t-quad, k): 16 n x 128 b x 4 t.
// ILP 4: each weight LDS feeds 4 t-packs (8 FMA2 per sw2 LDS.128).
// pt[] buffer is reused: standardized-x pack (read at iter p start) ->
// t-value pack (written at iter p end), same thread, same slot.
// grid = (Tt/4, Kk) = (64, 10), 128 threads (thread = b).
// ---------------------------------------------------------------------------
__global__ void __launch_bounds__(128, 1) fused_kernel(
    const float* __restrict__ x,
    const float* __restrict__ W1, const float* __restrict__ b1,
    const float* __restrict__ W2, const float* __restrict__ b2,
    const float* __restrict__ W3, const float* __restrict__ b3,
    float* __restrict__ out)
{
    extern __shared__ __align__(16) char dyn[];
    ulonglong2* sw2   = (ulonglong2*)dyn;              // [p*200 + o*10 + q]
    ulonglong2* sl1   = sw2 + SL1_OFF;                 // [p*20 + i] {w1,b1}
    ulonglong2* sl2e  = sw2 + SL2E_OFF;                // [p*20 + o] {b2,w3}
    ulonglong2* shead = sw2 + SHEAD_OFF;               // [p] {w3sum,b3}
    u64*   pt    = (u64*)(dyn + 30848);                // [(p*4+dt)*130 + b]
    float* xtile = (float*)(dyn + 30848 + PT_BYTES);   // [col*132 + b], col=n*4+dt
    float2* xcoef = (float2*)(dyn + 30848 + PT_BYTES + XT_BYTES);   // [64]
    float4* tcoef = (float4*)(dyn + 30848 + PT_BYTES + XT_BYTES + 512); // [32]

    __shared__ float sred[4][4];
    __shared__ unsigned int s_last;

    int tid = threadIdx.x;
    int b   = tid;
    int t0  = blockIdx.x * 4;
    int k   = blockIdx.y;

    // ---- weight load + pack (pack = {n0,n1} = {2p, 2p+1}) ----
    {
        const float* W2k = W2 + k * Nn * Hh * Hh;
        for (int idx = tid; idx < 1600; idx += 128) {
            int p = idx / 200, rem = idx % 200, o = rem / 10, q = rem % 10;
            const float* wa = W2k + ((2 * p)     * Hh + o) * Hh;
            const float* wb = W2k + ((2 * p + 1) * Hh + o) * Hh;
            ulonglong2 v;
            v.x = pk(wa[2 * q],     wb[2 * q]);
            v.y = pk(wa[2 * q + 1], wb[2 * q + 1]);
            sw2[idx] = v;
        }
        const float* W1k = W1 + k * Nn * Hh;
        const float* b1k = b1 + k * Nn * Hh;
        const float* b2k = b2 + k * Nn * Hh;
        const float* W3k = W3 + k * Nn * Hh;
        for (int idx = tid; idx < 160; idx += 128) {
            int p = idx / 20, i = idx % 20;
            ulonglong2 v;
            v.x = pk(W1k[(2 * p) * Hh + i], W1k[(2 * p + 1) * Hh + i]);
            v.y = pk(b1k[(2 * p) * Hh + i], b1k[(2 * p + 1) * Hh + i]);
            sl1[idx] = v;
            ulonglong2 e;
            e.x = pk(b2k[(2 * p) * Hh + i], b2k[(2 * p + 1) * Hh + i]);
            e.y = pk(W3k[(2 * p) * Hh + i], W3k[(2 * p + 1) * Hh + i]);
            sl2e[idx] = e;
        }
        if (tid < 8) {
            float sa = 0.f, sb = 0.f;
#pragma unroll
            for (int i = 0; i < Hh; i++) {
                sa += W3k[(2 * tid) * Hh + i];
                sb += W3k[(2 * tid + 1) * Hh + i];
            }
            ulonglong2 v;
            v.x = pk(sa, sb);
            v.y = pk(b3[k * Nn + 2 * tid], b3[k * Nn + 2 * tid + 1]);
            shead[tid] = v;
        }
    }

    // ---- x load: thread b loads 4 t x 16 n (256B contiguous per lane) ----
#pragma unroll
    for (int dt = 0; dt < 4; dt++) {
#pragma unroll
        for (int nq = 0; nq < 4; nq++) {
            float4 v = *(const float4*)(x + ((size_t)(b * Tt + t0 + dt)) * Nn + nq * 4);
            xtile[((nq * 4 + 0) * 4 + dt) * 132 + b] = v.x;
            xtile[((nq * 4 + 1) * 4 + dt) * 132 + b] = v.y;
            xtile[((nq * 4 + 2) * 4 + dt) * 132 + b] = v.z;
            xtile[((nq * 4 + 3) * 4 + dt) * 132 + b] = v.w;
        }
    }
    __syncthreads();

    // ---- x stats per (n,dt) column over b (ddof=1, no eps) ----
    {
        int col = tid >> 1, hf = tid & 1;   // 64 cols x 2 threads
        float S = 0.f, Q = 0.f;
#pragma unroll 8
        for (int i = 0; i < 64; i++) {
            float v = xtile[col * 132 + hf * 64 + i];
            S += v; Q = fmaf(v, v, Q);
        }
        S += __shfl_xor_sync(0xffffffffu, S, 1);
        Q += __shfl_xor_sync(0xffffffffu, Q, 1);
        if (hf == 0) {
            float mu = S * (1.f / 128.f);
            float ri = 1.f / sqrtf((Q - S * mu) * (1.f / 127.f));
            xcoef[col] = make_float2(ri, -mu * ri);
        }
    }
    __syncthreads();

    // ---- pack standardized x into pt (same-thread slot reuse later) ----
#pragma unroll
    for (int p = 0; p < 8; p++) {
#pragma unroll
        for (int dt = 0; dt < 4; dt++) {
            float2 c0 = xcoef[(2 * p) * 4 + dt];
            float2 c1 = xcoef[(2 * p + 1) * 4 + dt];
            float x0 = xtile[((2 * p) * 4 + dt) * 132 + b];
            float x1 = xtile[((2 * p + 1) * 4 + dt) * 132 + b];
            pt[(p * 4 + dt) * 130 + b] = pk(fmaf(x0, c0.x, c0.y), fmaf(x1, c1.x, c1.y));
        }
    }

    const u64 ZERO = 0ull;
    const u64 c005  = pk(0.05f, 0.05f);
    const u64 cn005 = pk(-0.05f, -0.05f);

    // ---- MLP loop: 8 n-pairs, 4 t-packs each (ILP 4 per weight LDS) ----
#pragma unroll 1
    for (int p = 0; p < 8; p++) {
        u64 xp[4];
#pragma unroll
        for (int dt = 0; dt < 4; dt++)
            xp[dt] = pt[(p * 4 + dt) * 130 + b];

        // layer 1 + streamed LN1 stats
        u64 h[4][Hh];
        u64 s1[4], q1[4];
#pragma unroll
        for (int dt = 0; dt < 4; dt++) { s1[dt] = ZERO; q1[dt] = ZERO; }
#pragma unroll
        for (int i = 0; i < Hh; i++) {
            ulonglong2 wb = sl1[p * 20 + i];
#pragma unroll
            for (int dt = 0; dt < 4; dt++) {
                u64 t; FMA2(t, xp[dt], wb.x, wb.y);
                t = relu2(t);
                h[dt][i] = t;
                ADD2(s1[dt], s1[dt], t);
                FMA2(q1[dt], t, t, q1[dt]);
            }
        }
        // LN1 in place
#pragma unroll
        for (int dt = 0; dt < 4; dt++) {
            u64 mu, nmu, ex, var;
            MUL2(mu,  s1[dt], c005);
            MUL2(nmu, s1[dt], cn005);
            MUL2(ex,  q1[dt], c005);
            FMA2(var, mu, nmu, ex);
            float2 vf = up(var);
            float rx = rsqrtf(vf.x + 1e-5f);
            float ry = rsqrtf(vf.y + 1e-5f);
            u64 r1 = pk(rx, ry);
            u64 v1; MUL2(v1, nmu, r1);
#pragma unroll
            for (int i = 0; i < Hh; i++)
                FMA2(h[dt][i], h[dt][i], r1, v1);
        }

        // layer 2; accumulators start at b2; stream LN2 stats + W3 dot
        u64 s2[4], q2[4], d3[4];
#pragma unroll
        for (int dt = 0; dt < 4; dt++) { s2[dt] = ZERO; q2[dt] = ZERO; d3[dt] = ZERO; }
#pragma unroll 2
        for (int o = 0; o < Hh; o++) {
            ulonglong2 bw = sl2e[p * 20 + o];   // {b2 pack, w3 pack}
            u64 a[4];
            a[0] = bw.x; a[1] = bw.x; a[2] = bw.x; a[3] = bw.x;
#pragma unroll
            for (int q = 0; q < 10; q++) {
                ulonglong2 wv = sw2[p * 200 + o * 10 + q];
#pragma unroll
                for (int dt = 0; dt < 4; dt++) {
                    FMA2(a[dt], h[dt][2 * q],     wv.x, a[dt]);
                    FMA2(a[dt], h[dt][2 * q + 1], wv.y, a[dt]);
                }
            }
#pragma unroll
            for (int dt = 0; dt < 4; dt++) {
                u64 h2 = relu2(a[dt]);
                ADD2(s2[dt], s2[dt], h2);
                FMA2(q2[dt], h2, h2, q2[dt]);
                FMA2(d3[dt], h2, bw.y, d3[dt]);
            }
        }

        // LN2 fold + head; overwrite pt slot with t-value pack
        ulonglong2 hd = shead[p];
#pragma unroll
        for (int dt = 0; dt < 4; dt++) {
            u64 mu2, nmu2, ex2, var2;
            MUL2(mu2,  s2[dt], c005);
            MUL2(nmu2, s2[dt], cn005);
            MUL2(ex2,  q2[dt], c005);
            FMA2(var2, mu2, nmu2, ex2);
            float2 vf = up(var2);
            float rx = rsqrtf(vf.x + 1e-5f);
            float ry = rsqrtf(vf.y + 1e-5f);
            u64 r2 = pk(rx, ry);
            u64 tmp; FMA2(tmp, nmu2, hd.x, d3[dt]);
            u64 o2;  FMA2(o2, r2, tmp, hd.y);
            pt[(p * 4 + dt) * 130 + b] = o2;
        }
    }
    __syncthreads();

    // ---- t stats per (p,dt) over b: per half {r, -mu*r} ----
    {
        int c = tid >> 2, sub = tid & 3;     // 32 cols x 4 threads
        float Sx = 0.f, Qx = 0.f, Sy = 0.f, Qy = 0.f;
#pragma unroll
        for (int i = 0; i < 32; i++) {
            float2 v = up(pt[c * 130 + sub * 32 + i]);
            Sx += v.x; Qx = fmaf(v.x, v.x, Qx);
            Sy += v.y; Qy = fmaf(v.y, v.y, Qy);
        }
#pragma unroll
        for (int o = 2; o; o >>= 1) {
            Sx += __shfl_xor_sync(0xffffffffu, Sx, o);
            Qx += __shfl_xor_sync(0xffffffffu, Qx, o);
            Sy += __shfl_xor_sync(0xffffffffu, Sy, o);
            Qy += __shfl_xor_sync(0xffffffffu, Qy, o);
        }
        if (sub == 0) {
            float mux = Sx * (1.f / 128.f);
            float rx  = 1.f / (sqrtf((Qx - Sx * mux) * (1.f / 127.f)) + 1e-8f);
            float muy = Sy * (1.f / 128.f);
            float ry  = 1.f / (sqrtf((Qy - Sy * muy) * (1.f / 127.f)) + 1e-8f);
            tcoef[c] = make_float4(rx, -mux * rx, ry, -muy * ry);
        }
    }
    __syncthreads();

    // ---- product over n per (b,dt); prod_marginals == 0 in fp32, so
    //      d^2 = prod_joint^2. block-reduce per dt. ----
    {
        int wid = tid >> 5, lane = tid & 31;
#pragma unroll
        for (int dt = 0; dt < 4; dt++) {
            float prod = 1.f;
#pragma unroll
            for (int p = 0; p < 8; p++) {
                float4 tc = tcoef[p * 4 + dt];
                float2 v  = up(pt[(p * 4 + dt) * 130 + b]);
                prod *= fmaf(v.x, tc.x, tc.y);
                prod *= fmaf(v.y, tc.z, tc.w);
            }
#pragma unroll
            for (int o = 16; o; o >>= 1)
                prod += __shfl_xor_sync(0xffffffffu, prod, o);
            if (lane == 0) sred[dt][wid] = prod;
        }
    }
    __syncthreads();
    if (tid < 4) {
        float pj = (sred[tid][0] + sred[tid][1] + sred[tid][2] + sred[tid][3]) * (1.f / 128.f);
        g_sq[k * Tt + t0 + tid] = pj * pj;
    }

    // ---- completion counter: last block reduces g_sq deterministically ----
    __threadfence();
    __syncthreads();
    if (tid == 0) {
        unsigned int t = atomicAdd(&g_ctr, 1u);
        s_last = (t == (unsigned int)(gridDim.x * gridDim.y - 1)) ? 1u : 0u;
    }
    __syncthreads();
    if (s_last) {
        __threadfence();
        float acc = 0.f;
        for (int i = tid; i < KT; i += 128) acc += g_sq[i];
#pragma unroll
        for (int o = 16; o; o >>= 1) acc += __shfl_xor_sync(0xffffffffu, acc, o);
        if ((tid & 31) == 0) sred[0][tid >> 5] = acc;
        __syncthreads();
        if (tid == 0) {
            out[0] = (sred[0][0] + sred[0][1] + sred[0][2] + sred[0][3]) * (1.f / (float)KT);
            g_ctr = 0u;   // reset for next graph replay
        }
    }
}

// ---------------------------------------------------------------------------
extern "C" void kernel_launch(void* const* d_in, const int* in_sizes, int n_in,
                              void* d_out, int out_size) {
    const float* x  = (const float*)d_in[0];
    const float* W1 = (const float*)d_in[1];
    const float* b1 = (const float*)d_in[2];
    const float* W2 = (const float*)d_in[3];
    const float* b2 = (const float*)d_in[4];
    const float* W3 = (const float*)d_in[5];
    const float* b3 = (const float*)d_in[6];

    cudaFuncSetAttribute(fused_kernel,
                         cudaFuncAttributeMaxDynamicSharedMemorySize, DSMEM_TOTAL);

    dim3 grid(Tt / 4, Kk);
    fused_kernel<<<grid, 128, DSMEM_TOTAL>>>(x, W1, b1, W2, b2, W3, b3, (float*)d_out);
}

// round 9
// speedup vs baseline: 1.1671x; 1.1341x over previous
#include <cuda_runtime.h>

// Problem constants
#define Bb   128
#define Tt   256
#define Nn   16
#define Kk   10
#define Hh   20
#define BT   32768          // Bb*Tt
#define KT   (Kk*Tt)        // 2560

typedef unsigned long long u64;

// Scratch (static device globals — no allocation)
// Sample index j = t*128 + b (b-fastest!)
__device__ float g_xs[Nn * BT];                    // standardized x, [n][j], 2 MB
__device__ float g_t [(size_t)Kk * Nn * BT];       // t values, [k][n][j], 20 MB
__device__ float g_sq[KT];                         // per-(k,t) squared diffs
__device__ float g_mu[Nn * Tt];                    // per-(t,n) mean, [n][t]
__device__ float g_ri[Nn * Tt];                    // per-(t,n) 1/std,  [n][t]
__device__ unsigned int g_ctr;                     // completion counter (zero-init)

// ---------------- packed f32x2 helpers ----------------
__device__ __forceinline__ u64 pk(float lo, float hi) {
    u64 r; asm("mov.b64 %0,{%1,%2};" : "=l"(r) : "f"(lo), "f"(hi)); return r;
}
__device__ __forceinline__ float2 up(u64 v) {
    float2 f; asm("mov.b64 {%0,%1},%2;" : "=f"(f.x), "=f"(f.y) : "l"(v)); return f;
}
#define FMA2(d,a,b,c) asm("fma.rn.f32x2 %0,%1,%2,%3;" : "=l"(d) : "l"(a), "l"(b), "l"(c))
#define ADD2(d,a,b)   asm("add.rn.f32x2 %0,%1,%2;"    : "=l"(d) : "l"(a), "l"(b))
#define MUL2(d,a,b)   asm("mul.rn.f32x2 %0,%1,%2;"    : "=l"(d) : "l"(a), "l"(b))

__device__ __forceinline__ u64 relu2(u64 v) {
    float2 f = up(v);
    return pk(fmaxf(f.x, 0.f), fmaxf(f.y, 0.f));
}

// ---------------------------------------------------------------------------
// Kernel 1a: per-(t,n) column stats over b (ddof=1). 4 threads per column,
// coalesced 128B warp loads; smem combine. Stats written in [n][t] layout.
// grid = 32 blocks x 512 threads.
// ---------------------------------------------------------------------------
__global__ void __launch_bounds__(512) stats_kernel(const float* __restrict__ x) {
    __shared__ float ss[4][128], sq[4][128];
    int q  = threadIdx.x >> 7;            // 0..3 (b sub-range)
    int cl = threadIdx.x & 127;
    int gc = blockIdx.x * 128 + cl;       // global column = t*16+n

    float s = 0.f, qq = 0.f;
#pragma unroll 8
    for (int b = q * 32; b < q * 32 + 32; b++) {
        float v = x[b * 4096 + gc];
        s += v; qq = fmaf(v, v, qq);
    }
    ss[q][cl] = s; sq[q][cl] = qq;
    __syncthreads();
    if (threadIdx.x < 128) {
        float S = ss[0][cl] + ss[1][cl] + ss[2][cl] + ss[3][cl];
        float Q = sq[0][cl] + sq[1][cl] + sq[2][cl] + sq[3][cl];
        float mu = S * (1.f / 128.f);
        float ri = 1.f / sqrtf((Q - S * mu) * (1.f / 127.f));
        int t = gc >> 4, n = gc & 15;
        g_mu[n * Tt + t] = mu;
        g_ri[n * Tt + t] = ri;
    }
}

// ---------------------------------------------------------------------------
// Kernel 1b: transpose + normalize: x[b][t][n] -> g_xs[n][t*128+b].
// Tile = 32 b x 8 t x 16 n. Loads and stores fully coalesced.
// grid = (4 b-chunks, 32 t-chunks), 256 threads.
// ---------------------------------------------------------------------------
__global__ void __launch_bounds__(256) transpose_kernel(const float* __restrict__ x) {
    __shared__ float tile[8][16][33];   // [t][n][b]
    int b0 = blockIdx.x * 32;
    int t0 = blockIdx.y * 8;
    int tid = threadIdx.x;

    // load 4096 floats (1024 float4, 4/thread); warp reads 512B contiguous
#pragma unroll
    for (int r = 0; r < 4; r++) {
        int f  = r * 256 + tid;
        int n4 = f & 3;
        int tl = (f >> 2) & 7;
        int bl = f >> 5;
        float4 v = *(const float4*)(x + ((size_t)((b0 + bl) * Tt + t0 + tl)) * Nn + n4 * 4);
        tile[tl][n4 * 4 + 0][bl] = v.x;
        tile[tl][n4 * 4 + 1][bl] = v.y;
        tile[tl][n4 * 4 + 2][bl] = v.z;
        tile[tl][n4 * 4 + 3][bl] = v.w;
    }
    __syncthreads();

    // store: plane (n,tl) = 32 consecutive b = 128B; normalize on the way out
#pragma unroll
    for (int r = 0; r < 4; r++) {
        int f = r * 256 + tid;
        int plane = f >> 3;         // 0..127
        int q = f & 7;              // float4 index within 32 b
        int n  = plane >> 3;
        int tl = plane & 7;
        float mu = g_mu[n * Tt + t0 + tl];
        float ri = g_ri[n * Tt + t0 + tl];
        float4 o;
        o.x = (tile[tl][n][q * 4 + 0] - mu) * ri;
        o.y = (tile[tl][n][q * 4 + 1] - mu) * ri;
        o.z = (tile[tl][n][q * 4 + 2] - mu) * ri;
        o.w = (tile[tl][n][q * 4 + 3] - mu) * ri;
        *(float4*)(g_xs + n * BT + (t0 + tl) * 128 + b0 + q * 4) = o;
    }
}

// ---------------------------------------------------------------------------
// Kernel 2: MLP sweep, packed f32x2, 8 samples per thread (4 packed pairs).
// Identical math to R6; j is now t*128+b (thread's 8 samples = 8 b's, one t).
// Block = 128. grid = (K*N, 32).
// ---------------------------------------------------------------------------
__global__ void __launch_bounds__(128) mlp_kernel(
    const float* __restrict__ W1, const float* __restrict__ b1,
    const float* __restrict__ W2, const float* __restrict__ b2,
    const float* __restrict__ W3, const float* __restrict__ b3)
{
    __shared__ __align__(16) float sw2f[Hh][Hh * 2];   // [o][2i..2i+1] = dup W2[o][i]
    __shared__ __align__(16) float sw1b1[Hh][4];       // {w1,w1,b1,b1}
    __shared__ __align__(16) float sb2w3[Hh][4];       // {b2,b2,w3,w3}
    __shared__ __align__(16) float sc[4];              // {w3sum,w3sum,b3,b3}

    int kn = blockIdx.x;          // k*N + n
    int n  = kn & 15;
    int k  = kn >> 4;
    int tid = threadIdx.x;

    for (int idx = tid; idx < Hh * Hh; idx += 128) {
        float v = W2[kn * Hh * Hh + idx];
        int o = idx / Hh, i = idx % Hh;
        sw2f[o][2 * i] = v; sw2f[o][2 * i + 1] = v;
    }
    if (tid < Hh) {
        float w = W1[kn * Hh + tid], b = b1[kn * Hh + tid];
        sw1b1[tid][0] = w; sw1b1[tid][1] = w;
        sw1b1[tid][2] = b; sw1b1[tid][3] = b;
        float bb = b2[kn * Hh + tid];
        float w3 = W3[kn * Hh + tid];
        sb2w3[tid][0] = bb; sb2w3[tid][1] = bb;
        sb2w3[tid][2] = w3; sb2w3[tid][3] = w3;
    }
    if (tid == 0) {
        float s3 = 0.f;
#pragma unroll
        for (int i = 0; i < Hh; i++) s3 += W3[kn * Hh + i];
        sc[0] = s3; sc[1] = s3;
        float bb3 = b3[kn];
        sc[2] = bb3; sc[3] = bb3;
    }
    __syncthreads();

    const float* xs = g_xs + n * BT;
    float* tout = g_t + (size_t)(k * Nn + n) * BT;

    int j0 = (blockIdx.y * 128 + tid) * 8;
    float4 xa = *(const float4*)(xs + j0);
    float4 xb = *(const float4*)(xs + j0 + 4);
    u64 xp[4];
    xp[0] = pk(xa.x, xa.y); xp[1] = pk(xa.z, xa.w);
    xp[2] = pk(xb.x, xb.y); xp[3] = pk(xb.z, xb.w);

    const u64 ZERO = 0ull;
    const u64 c005  = pk(0.05f, 0.05f);
    const u64 cn005 = pk(-0.05f, -0.05f);

    // ---- layer 1 with streamed LN1 stats ----
    u64 h[4][Hh];
    u64 s1[4], q1[4];
#pragma unroll
    for (int p = 0; p < 4; p++) { s1[p] = ZERO; q1[p] = ZERO; }
#pragma unroll
    for (int i = 0; i < Hh; i++) {
        ulonglong2 wb = *(const ulonglong2*)&sw1b1[i][0];
#pragma unroll
        for (int p = 0; p < 4; p++) {
            u64 t; FMA2(t, xp[p], wb.x, wb.y);
            t = relu2(t);
            h[p][i] = t;
            ADD2(s1[p], s1[p], t);
            FMA2(q1[p], t, t, q1[p]);
        }
    }
    // LN1 in place
#pragma unroll
    for (int p = 0; p < 4; p++) {
        u64 mu, nmu, ex, var;
        MUL2(mu,  s1[p], c005);
        MUL2(nmu, s1[p], cn005);
        MUL2(ex,  q1[p], c005);
        FMA2(var, mu, nmu, ex);     // E[h^2] - mu^2 (biased)
        float2 vf = up(var);
        float rx = rsqrtf(vf.x + 1e-5f);
        float ry = rsqrtf(vf.y + 1e-5f);
        u64 r1 = pk(rx, ry);
        u64 v1; MUL2(v1, nmu, r1);
#pragma unroll
        for (int i = 0; i < Hh; i++)
            FMA2(h[p][i], h[p][i], r1, v1);
    }

    // ---- layer 2; accumulators start at b2; stream LN2 stats + W3 dot ----
    u64 s2[4], q2[4], d3[4];
#pragma unroll
    for (int p = 0; p < 4; p++) { s2[p] = ZERO; q2[p] = ZERO; d3[p] = ZERO; }

#pragma unroll 2
    for (int o = 0; o < Hh; o++) {
        const ulonglong2* wrow = (const ulonglong2*)&sw2f[o][0];
        ulonglong2 bw = *(const ulonglong2*)&sb2w3[o][0];   // {b2 dup, w3 dup}
        u64 a[4];
        a[0] = bw.x; a[1] = bw.x; a[2] = bw.x; a[3] = bw.x;
#pragma unroll
        for (int q = 0; q < Hh / 2; q++) {
            ulonglong2 wv = wrow[q];
#pragma unroll
            for (int p = 0; p < 4; p++) {
                FMA2(a[p], h[p][2 * q],     wv.x, a[p]);
                FMA2(a[p], h[p][2 * q + 1], wv.y, a[p]);
            }
        }
#pragma unroll
        for (int p = 0; p < 4; p++) {
            u64 h2 = relu2(a[p]);
            ADD2(s2[p], s2[p], h2);
            FMA2(q2[p], h2, h2, q2[p]);
            FMA2(d3[p], h2, bw.y, d3[p]);
        }
    }

    // ---- LN2 fold + head ----
    u64 w3s = *(const u64*)&sc[0];
    u64 b3d = *(const u64*)&sc[2];
    float outv[8];
#pragma unroll
    for (int p = 0; p < 4; p++) {
        u64 mu2, nmu2, ex2, var2;
        MUL2(mu2,  s2[p], c005);
        MUL2(nmu2, s2[p], cn005);
        MUL2(ex2,  q2[p], c005);
        FMA2(var2, mu2, nmu2, ex2);
        float2 vf = up(var2);
        float rx = rsqrtf(vf.x + 1e-5f);
        float ry = rsqrtf(vf.y + 1e-5f);
        u64 r2 = pk(rx, ry);
        u64 tmp; FMA2(tmp, nmu2, w3s, d3[p]);
        u64 o2;  FMA2(o2, r2, tmp, b3d);
        float2 of = up(o2);
        outv[2 * p] = of.x; outv[2 * p + 1] = of.y;
    }
    *(float4*)(tout + j0)     = make_float4(outv[0], outv[1], outv[2], outv[3]);
    *(float4*)(tout + j0 + 4) = make_float4(outv[4], outv[5], outv[6], outv[7]);
}

// ---------------------------------------------------------------------------
// Kernel 3: penalty. g_t is [k][n][t][b] (b contiguous!): each (n,t) plane
// is 512B; warp-load = one plane, 100% sector efficiency.
// prod_marginals underflows to exactly 0 in fp32, so d^2 = prod_joint^2.
// grid = K*T/4 = 640 blocks, 128 threads (4 warps; warp = one dt).
// ---------------------------------------------------------------------------
#define PB 4

__global__ void __launch_bounds__(128) penalty_kernel(float* __restrict__ out) {
    int bid = blockIdx.x;            // 0..639
    int k   = bid >> 6;
    int tt0 = (bid & 63) * PB;

    __shared__ float s[64][132];     // [n*4+dt][b]
    __shared__ float sac[64][2];     // per col: {r, -mu*r}
    __shared__ float part[4];
    __shared__ unsigned int s_last;

    int tid = threadIdx.x;
    int wid = tid >> 5, lane = tid & 31;

    // load: warp-inst = one (n,dt) plane (32 lanes x float4 = 512B contiguous)
#pragma unroll
    for (int pp = 0; pp < 16; pp++) {
        int plane = pp * 4 + wid;            // = n*4 + dt
        int n  = plane >> 2;
        int dt = plane & 3;
        const float4* src = (const float4*)(g_t +
            ((size_t)(k * 16 + n)) * BT + (tt0 + dt) * 128);
        float4 v = src[lane];
        *(float4*)&s[plane][lane * 4] = v;
    }
    __syncthreads();

    // fused stats pass: sum + sumsq over b (2 threads per column)
    int col = tid >> 1, hf = tid & 1;
    float S = 0.f, Q = 0.f;
#pragma unroll 8
    for (int i = 0; i < 64; i++) {
        float v = s[col][hf * 64 + i];
        S += v; Q = fmaf(v, v, Q);
    }
    S += __shfl_xor_sync(0xffffffffu, S, 1);
    Q += __shfl_xor_sync(0xffffffffu, Q, 1);
    if (hf == 0) {
        float mu = S * (1.f / 128.f);
        float r  = 1.f / (sqrtf((Q - S * mu) * (1.f / 127.f)) + 1e-8f);
        sac[col][0] = r;
        sac[col][1] = -mu * r;
    }
    __syncthreads();

    // product pass: warp = dt; coefficients in registers (broadcast LDS)
    int dt = wid;
    float2 ac[16];
#pragma unroll
    for (int n = 0; n < 16; n++)
        ac[n] = *(const float2*)&sac[n * 4 + dt][0];

    float acc = 0.f;
#pragma unroll
    for (int j = 0; j < 4; j++) {
        int bb = lane + 32 * j;               // stride-1 lanes: conflict-free
        float prod = fmaf(s[0 * 4 + dt][bb], ac[0].x, ac[0].y);
#pragma unroll
        for (int n = 1; n < 16; n++)
            prod *= fmaf(s[n * 4 + dt][bb], ac[n].x, ac[n].y);
        acc += prod;
    }
#pragma unroll
    for (int o = 16; o; o >>= 1) acc += __shfl_xor_sync(0xffffffffu, acc, o);
    if (lane == 0) {
        float pj = acc * (1.f / 128.f);       // d = 0 - pj; d^2 = pj^2
        g_sq[k * Tt + tt0 + dt] = pj * pj;
    }

    // completion counter: last block reduces g_sq deterministically
    __threadfence();
    __syncthreads();
    if (tid == 0) {
        unsigned int t = atomicAdd(&g_ctr, 1u);
        s_last = (t == (unsigned int)(Kk * Tt / PB - 1)) ? 1u : 0u;
    }
    __syncthreads();
    if (s_last) {
        __threadfence();
        float facc = 0.f;
        for (int i = tid; i < KT; i += 128) facc += g_sq[i];
#pragma unroll
        for (int o = 16; o; o >>= 1) facc += __shfl_xor_sync(0xffffffffu, facc, o);
        if ((tid & 31) == 0) part[tid >> 5] = facc;
        __syncthreads();
        if (tid == 0) {
            out[0] = (part[0] + part[1] + part[2] + part[3]) * (1.f / (float)KT);
            g_ctr = 0u;   // reset for next graph replay
        }
    }
}

// ---------------------------------------------------------------------------
extern "C" void kernel_launch(void* const* d_in, const int* in_sizes, int n_in,
                              void* d_out, int out_size) {
    const float* x  = (const float*)d_in[0];
    const float* W1 = (const float*)d_in[1];
    const float* b1 = (const float*)d_in[2];
    const float* W2 = (const float*)d_in[3];
    const float* b2 = (const float*)d_in[4];
    const float* W3 = (const float*)d_in[5];
    const float* b3 = (const float*)d_in[6];

    stats_kernel<<<32, 512>>>(x);

    dim3 g1(4, 32);
    transpose_kernel<<<g1, 256>>>(x);

    dim3 g2(Kk * Nn, 32);
    mlp_kernel<<<g2, 128>>>(W1, b1, W2, b2, W3, b3);

    penalty_kernel<<<KT / PB, 128>>>((float*)d_out);
}